// round 1
// baseline (speedup 1.0000x reference)
#include <cuda_runtime.h>
#include <math.h>

#define BB 256
#define TT 64
#define NN 128
#define MM 256
#define INROW 129   // N + YD

// ---------------- scratch (device globals; no allocation) ----------------
__device__ float g_Xp[BB*TT*NN];     // [b][t][n]  precomputed X_nt @ WU_e_x^T
__device__ float g_Xe[BB*TT*MM];     // [b][t][m]  encoder outputs
__device__ float g_Xd[BB*TT*MM];     // [b][t][m]  precomputed Xe @ WU_d_x^T
__device__ float g_h[2][BB*MM];
__device__ float g_c[2][BB*MM];
__device__ float g_xin[BB*NN];
__device__ float g_hsW[BB*MM];
__device__ float g_ctx[BB*MM];
__device__ float g_yt[BB];

__device__ __forceinline__ float sigm(float x) { return 1.0f / (1.0f + expf(-x)); }

__device__ __forceinline__ float wredsum(float v) {
    #pragma unroll
    for (int o = 16; o > 0; o >>= 1) v += __shfl_down_sync(0xffffffffu, v, o);
    return v;
}
__device__ __forceinline__ float wredmax(float v) {
    #pragma unroll
    for (int o = 16; o > 0; o >>= 1) v = fmaxf(v, __shfl_down_sync(0xffffffffu, v, o));
    return v;
}

// ---------------- init: zero state buffers ----------------
__global__ void k_init() {
    int idx = blockIdx.x * blockDim.x + threadIdx.x;  // 256*256 = 65536 = BB*MM
    g_h[0][idx] = 0.f; g_h[1][idx] = 0.f;
    g_c[0][idx] = 0.f; g_c[1][idx] = 0.f;
}

// ---------------- precompute Xp[b][t][n] = sum_tp X[b,tp,n] * WU_e[t, 512+tp] ----------------
__global__ void k_xp(const float* __restrict__ inp, const float* __restrict__ WU_e) {
    __shared__ float WUx[64*64];   // [t][tp]
    __shared__ float Xs[64*128];   // [tp][n]
    int b = blockIdx.x;
    int tid = threadIdx.x;  // 128
    for (int idx = tid; idx < 4096; idx += 128) {
        int t = idx >> 6, tp = idx & 63;
        WUx[idx] = WU_e[t*576 + 512 + tp];
    }
    for (int idx = tid; idx < 8192; idx += 128) {
        int tp = idx >> 7, n = idx & 127;
        Xs[idx] = inp[b*TT*INROW + tp*INROW + n];
    }
    __syncthreads();
    float acc[64];
    #pragma unroll
    for (int t = 0; t < 64; ++t) acc[t] = 0.f;
    int n = tid;
    for (int tp = 0; tp < 64; ++tp) {
        float xv = Xs[tp*128 + n];
        #pragma unroll
        for (int t = 0; t < 64; ++t) acc[t] += xv * WUx[t*64 + tp];
    }
    #pragma unroll
    for (int t = 0; t < 64; ++t) g_Xp[(b*TT + t)*NN + n] = acc[t];
}

// ---------------- encoder attention (per step): hsW + E + softmax + x*alpha ----------------
__global__ void k_enc_att(const float* __restrict__ inp, const float* __restrict__ WU_e,
                          const float* __restrict__ v_e, int step, int par) {
    int b = blockIdx.x;
    int tid = threadIdx.x;          // 128
    int w = tid >> 5, l = tid & 31;
    __shared__ float hs[512];
    __shared__ float hsW_s[64];
    __shared__ float ves[64];
    __shared__ float redm[4], reds[4];
    const float* hb = g_h[par] + b*MM;
    const float* cb = g_c[par] + b*MM;
    hs[tid]       = hb[tid];
    hs[tid + 128] = hb[tid + 128];
    hs[tid + 256] = cb[tid];
    hs[tid + 384] = cb[tid + 128];
    if (tid < 64) ves[tid] = v_e[tid];
    __syncthreads();
    // hsW[t] = sum_k hs[k] * WU_e[t,k], t handled warp-wise
    for (int t = w*16; t < w*16 + 16; ++t) {
        const float* row = WU_e + t*576;
        float s = 0.f;
        #pragma unroll
        for (int k = l; k < 512; k += 32) s += hs[k] * row[k];
        s = wredsum(s);
        if (l == 0) hsW_s[t] = s;
    }
    __syncthreads();
    int n = tid;
    float e = 0.f;
    const float* xp = g_Xp + b*TT*NN + n;
    #pragma unroll 8
    for (int t = 0; t < 64; ++t) e += ves[t] * tanhf(hsW_s[t] + xp[t*NN]);
    // softmax over n (128 threads)
    float m = wredmax(e);
    if (l == 0) redm[w] = m;
    __syncthreads();
    m = fmaxf(fmaxf(redm[0], redm[1]), fmaxf(redm[2], redm[3]));
    float p = expf(e - m);
    float s = wredsum(p);
    if (l == 0) reds[w] = s;
    __syncthreads();
    float tot = reds[0] + reds[1] + reds[2] + reds[3];
    float alpha = p / tot;
    g_xin[b*NN + n] = inp[b*TT*INROW + step*INROW + n] * alpha;
}

// ---------------- encoder gates GEMM + fused LSTM ----------------
// grid (8, 16): 32 batch x (16 m per gate -> 64 cols). 128 threads, 4x4 per thread.
__global__ void k_enc_gates(const float* __restrict__ Wih, const float* __restrict__ Whh,
                            const float* __restrict__ bih, const float* __restrict__ bhh,
                            int step, int par) {
    int bb = blockIdx.x, mo = blockIdx.y;
    int tid = threadIdx.x;
    int ty = tid >> 4, tx = tid & 15;
    __shared__ float A_s[32][36];
    __shared__ float W_s[32][68];
    float acc[4][4];
    #pragma unroll
    for (int i = 0; i < 4; ++i)
        #pragma unroll
        for (int j = 0; j < 4; ++j) acc[i][j] = 0.f;
    const float* hsrc = g_h[par];
    for (int kc = 0; kc < 384; kc += 32) {
        for (int idx = tid; idx < 1024; idx += 128) {
            int bi = idx >> 5, kk = idx & 31;
            int k = kc + kk, gb = bb*32 + bi;
            A_s[kk][bi] = (k < 128) ? g_xin[gb*NN + k] : hsrc[gb*MM + (k - 128)];
        }
        for (int idx = tid; idx < 2048; idx += 128) {
            int co = idx >> 5, kk = idx & 31;
            int row = (co >> 4)*256 + mo*16 + (co & 15);
            int k = kc + kk;
            W_s[kk][co] = (k < 128) ? Wih[row*128 + k] : Whh[row*256 + (k - 128)];
        }
        __syncthreads();
        #pragma unroll
        for (int kk = 0; kk < 32; ++kk) {
            float4 a = *(const float4*)&A_s[kk][ty*4];
            float4 w = *(const float4*)&W_s[kk][tx*4];
            acc[0][0] += a.x*w.x; acc[0][1] += a.x*w.y; acc[0][2] += a.x*w.z; acc[0][3] += a.x*w.w;
            acc[1][0] += a.y*w.x; acc[1][1] += a.y*w.y; acc[1][2] += a.y*w.z; acc[1][3] += a.y*w.w;
            acc[2][0] += a.z*w.x; acc[2][1] += a.z*w.y; acc[2][2] += a.z*w.z; acc[2][3] += a.z*w.w;
            acc[3][0] += a.w*w.x; acc[3][1] += a.w*w.y; acc[3][2] += a.w*w.z; acc[3][3] += a.w*w.w;
        }
        __syncthreads();
    }
    // stash to smem, remap for LSTM elementwise (all 4 gates per (b,m) in block)
    #pragma unroll
    for (int i = 0; i < 4; ++i)
        #pragma unroll
        for (int j = 0; j < 4; ++j) W_s[ty*4 + i][tx*4 + j] = acc[i][j];
    __syncthreads();
    for (int idx = tid; idx < 512; idx += 128) {
        int bi = idx >> 4, ml = idx & 15;
        int gb = bb*32 + bi, m = mo*16 + ml;
        float gi = W_s[bi][ml]      + bih[m]       + bhh[m];
        float gf = W_s[bi][16 + ml] + bih[256 + m] + bhh[256 + m];
        float gg = W_s[bi][32 + ml] + bih[512 + m] + bhh[512 + m];
        float go = W_s[bi][48 + ml] + bih[768 + m] + bhh[768 + m];
        float cold = g_c[par][gb*MM + m];
        float cn = sigm(gf)*cold + sigm(gi)*tanhf(gg);
        float hn = sigm(go)*tanhf(cn);
        g_c[par ^ 1][gb*MM + m] = cn;
        g_h[par ^ 1][gb*MM + m] = hn;
        g_Xe[(gb*TT + step)*MM + m] = hn;
    }
}

// ---------------- precompute Xd[b][t][m] = sum_k Xe[b,t,k] * WU_d[m, 512+k] ----------------
// rows R = b*64+t (16384), tiled 64x64, grid (256, 4), 256 threads 4x4/thread
__global__ void k_xd(const float* __restrict__ WU_d) {
    int rb = blockIdx.x, ob = blockIdx.y;
    int tid = threadIdx.x;
    int ty = tid >> 4, tx = tid & 15;
    __shared__ float A_s[32][68];
    __shared__ float W_s[32][68];
    float acc[4][4];
    #pragma unroll
    for (int i = 0; i < 4; ++i)
        #pragma unroll
        for (int j = 0; j < 4; ++j) acc[i][j] = 0.f;
    for (int kc = 0; kc < 256; kc += 32) {
        for (int idx = tid; idx < 2048; idx += 256) {
            int ri = idx >> 5, kk = idx & 31;
            A_s[kk][ri] = g_Xe[(rb*64 + ri)*MM + kc + kk];
        }
        for (int idx = tid; idx < 2048; idx += 256) {
            int co = idx >> 5, kk = idx & 31;
            W_s[kk][co] = WU_d[(ob*64 + co)*768 + 512 + kc + kk];
        }
        __syncthreads();
        #pragma unroll
        for (int kk = 0; kk < 32; ++kk) {
            float4 a = *(const float4*)&A_s[kk][ty*4];
            float4 w = *(const float4*)&W_s[kk][tx*4];
            acc[0][0] += a.x*w.x; acc[0][1] += a.x*w.y; acc[0][2] += a.x*w.z; acc[0][3] += a.x*w.w;
            acc[1][0] += a.y*w.x; acc[1][1] += a.y*w.y; acc[1][2] += a.y*w.z; acc[1][3] += a.y*w.w;
            acc[2][0] += a.z*w.x; acc[2][1] += a.z*w.y; acc[2][2] += a.z*w.z; acc[2][3] += a.z*w.w;
            acc[3][0] += a.w*w.x; acc[3][1] += a.w*w.y; acc[3][2] += a.w*w.z; acc[3][3] += a.w*w.w;
        }
        __syncthreads();
    }
    #pragma unroll
    for (int i = 0; i < 4; ++i)
        #pragma unroll
        for (int j = 0; j < 4; ++j)
            g_Xd[(rb*64 + ty*4 + i)*MM + ob*64 + tx*4 + j] = acc[i][j];
}

// ---------------- decoder hsW GEMM: (B,512)[h|c] @ WU_d[:, :512]^T -> (B,256) ----------------
// grid (16, 8), tile 16b x 32o, 128 threads, 2x2/thread
__global__ void k_dec_hsw(const float* __restrict__ WU_d, int par) {
    int rb = blockIdx.x, ob = blockIdx.y;
    int tid = threadIdx.x;
    int ty = tid >> 4, tx = tid & 15;
    __shared__ float A_s[32][20];
    __shared__ float W_s[32][36];
    float a00 = 0.f, a01 = 0.f, a10 = 0.f, a11 = 0.f;
    for (int kc = 0; kc < 512; kc += 32) {
        for (int idx = tid; idx < 512; idx += 128) {
            int ri = idx >> 5, kk = idx & 31;
            int k = kc + kk, gb = rb*16 + ri;
            A_s[kk][ri] = (k < 256) ? g_h[par][gb*MM + k] : g_c[par][gb*MM + k - 256];
        }
        for (int idx = tid; idx < 1024; idx += 128) {
            int co = idx >> 5, kk = idx & 31;
            W_s[kk][co] = WU_d[(ob*32 + co)*768 + kc + kk];
        }
        __syncthreads();
        #pragma unroll
        for (int kk = 0; kk < 32; ++kk) {
            float2 a = *(const float2*)&A_s[kk][ty*2];
            float2 w = *(const float2*)&W_s[kk][tx*2];
            a00 += a.x*w.x; a01 += a.x*w.y; a10 += a.y*w.x; a11 += a.y*w.y;
        }
        __syncthreads();
    }
    int r0 = rb*16 + ty*2, o0 = ob*32 + tx*2;
    g_hsW[r0*MM + o0] = a00;       g_hsW[r0*MM + o0 + 1] = a01;
    g_hsW[(r0+1)*MM + o0] = a10;   g_hsW[(r0+1)*MM + o0 + 1] = a11;
}

// ---------------- decoder attention: l, beta, ctx, y_tilde ----------------
__global__ void k_dec_att(const float* __restrict__ inp, const float* __restrict__ v_d,
                          const float* __restrict__ wbt, int step, int par) {
    int b = blockIdx.x;
    int tid = threadIdx.x;   // 256
    int w = tid >> 5, l = tid & 31;
    __shared__ float hsw_s[256], vds[256], l_s[64], beta_s[64], reds[8];
    hsw_s[tid] = g_hsW[b*MM + tid];
    vds[tid] = v_d[tid];
    __syncthreads();
    for (int t = w; t < 64; t += 8) {
        const float* xd = g_Xd + (b*TT + t)*MM;
        float s = 0.f;
        #pragma unroll
        for (int m = l; m < 256; m += 32) s += vds[m] * tanhf(hsw_s[m] + xd[m]);
        s = wredsum(s);
        if (l == 0) l_s[t] = s;
    }
    __syncthreads();
    if (tid < 32) {
        float a0 = l_s[tid], a1 = l_s[tid + 32];
        float mx = wredmax(fmaxf(a0, a1));
        mx = __shfl_sync(0xffffffffu, mx, 0);
        float p0 = expf(a0 - mx), p1 = expf(a1 - mx);
        float sm = wredsum(p0 + p1);
        sm = __shfl_sync(0xffffffffu, sm, 0);
        beta_s[tid] = p0 / sm;
        beta_s[tid + 32] = p1 / sm;
    }
    __syncthreads();
    float c = 0.f;
    const float* xe = g_Xe + b*TT*MM + tid;
    #pragma unroll 8
    for (int t = 0; t < 64; ++t) c += beta_s[t] * xe[t*MM];
    g_ctx[b*MM + tid] = c;
    float part = wbt[1 + tid] * c;
    part = wredsum(part);
    if (l == 0) reds[w] = part;
    __syncthreads();
    if (tid == 0) {
        float tot = 0.f;
        #pragma unroll
        for (int i = 0; i < 8; ++i) tot += reds[i];
        g_yt[b] = wbt[0] * inp[b*TT*INROW + step*INROW + 128] + tot;
    }
}

// ---------------- decoder gates GEMM (K=256) + fused LSTM ----------------
__global__ void k_dec_gates(const float* __restrict__ Wihd, const float* __restrict__ Whh,
                            const float* __restrict__ bih, const float* __restrict__ bhh,
                            int par) {
    int bb = blockIdx.x, mo = blockIdx.y;
    int tid = threadIdx.x;
    int ty = tid >> 4, tx = tid & 15;
    __shared__ float A_s[32][36];
    __shared__ float W_s[32][68];
    float acc[4][4];
    #pragma unroll
    for (int i = 0; i < 4; ++i)
        #pragma unroll
        for (int j = 0; j < 4; ++j) acc[i][j] = 0.f;
    const float* hsrc = g_h[par];
    for (int kc = 0; kc < 256; kc += 32) {
        for (int idx = tid; idx < 1024; idx += 128) {
            int bi = idx >> 5, kk = idx & 31;
            A_s[kk][bi] = hsrc[(bb*32 + bi)*MM + kc + kk];
        }
        for (int idx = tid; idx < 2048; idx += 128) {
            int co = idx >> 5, kk = idx & 31;
            int row = (co >> 4)*256 + mo*16 + (co & 15);
            W_s[kk][co] = Whh[row*256 + kc + kk];
        }
        __syncthreads();
        #pragma unroll
        for (int kk = 0; kk < 32; ++kk) {
            float4 a = *(const float4*)&A_s[kk][ty*4];
            float4 w = *(const float4*)&W_s[kk][tx*4];
            acc[0][0] += a.x*w.x; acc[0][1] += a.x*w.y; acc[0][2] += a.x*w.z; acc[0][3] += a.x*w.w;
            acc[1][0] += a.y*w.x; acc[1][1] += a.y*w.y; acc[1][2] += a.y*w.z; acc[1][3] += a.y*w.w;
            acc[2][0] += a.z*w.x; acc[2][1] += a.z*w.y; acc[2][2] += a.z*w.z; acc[2][3] += a.z*w.w;
            acc[3][0] += a.w*w.x; acc[3][1] += a.w*w.y; acc[3][2] += a.w*w.z; acc[3][3] += a.w*w.w;
        }
        __syncthreads();
    }
    #pragma unroll
    for (int i = 0; i < 4; ++i)
        #pragma unroll
        for (int j = 0; j < 4; ++j) W_s[ty*4 + i][tx*4 + j] = acc[i][j];
    __syncthreads();
    for (int idx = tid; idx < 512; idx += 128) {
        int bi = idx >> 4, ml = idx & 15;
        int gb = bb*32 + bi, m = mo*16 + ml;
        float yt = g_yt[gb];
        float gi = W_s[bi][ml]      + bih[m]       + bhh[m]       + yt*Wihd[m];
        float gf = W_s[bi][16 + ml] + bih[256 + m] + bhh[256 + m] + yt*Wihd[256 + m];
        float gg = W_s[bi][32 + ml] + bih[512 + m] + bhh[512 + m] + yt*Wihd[512 + m];
        float go = W_s[bi][48 + ml] + bih[768 + m] + bhh[768 + m] + yt*Wihd[768 + m];
        float cold = g_c[par][gb*MM + m];
        float cn = sigm(gf)*cold + sigm(gi)*tanhf(gg);
        float hn = sigm(go)*tanhf(cn);
        g_c[par ^ 1][gb*MM + m] = cn;
        g_h[par ^ 1][gb*MM + m] = hn;
    }
}

// ---------------- final projection ----------------
__global__ void k_final(const float* __restrict__ WbW, const float* __restrict__ Wbb,
                        const float* __restrict__ vbW, const float* __restrict__ vbb,
                        float* __restrict__ out, int par) {
    int b = blockIdx.x;
    int tid = threadIdx.x;   // 256
    int w = tid >> 5, l = tid & 31;
    __shared__ float hc[512];
    __shared__ float hid[256];
    __shared__ float reds[8];
    hc[tid]       = g_h[par][b*MM + tid];
    hc[256 + tid] = g_ctx[b*MM + tid];
    __syncthreads();
    for (int p = w*32; p < w*32 + 32; ++p) {
        const float* row = WbW + p*512;
        float s = 0.f;
        #pragma unroll
        for (int k = l; k < 512; k += 32) s += hc[k] * row[k];
        s = wredsum(s);
        if (l == 0) hid[p] = s + Wbb[p];
    }
    __syncthreads();
    float part = hid[tid] * vbW[tid];
    part = wredsum(part);
    if (l == 0) reds[w] = part;
    __syncthreads();
    if (tid == 0) {
        float tot = 0.f;
        #pragma unroll
        for (int i = 0; i < 8; ++i) tot += reds[i];
        out[b] = tot + vbb[0];
    }
}

// ---------------- launcher ----------------
extern "C" void kernel_launch(void* const* d_in, const int* in_sizes, int n_in,
                              void* d_out, int out_size) {
    const float* inp   = (const float*)d_in[0];
    const float* WU_e  = (const float*)d_in[1];
    const float* v_e   = (const float*)d_in[2];
    const float* Wih_e = (const float*)d_in[3];
    const float* Whh_e = (const float*)d_in[4];
    const float* bih_e = (const float*)d_in[5];
    const float* bhh_e = (const float*)d_in[6];
    const float* WU_d  = (const float*)d_in[7];
    const float* v_d   = (const float*)d_in[8];
    const float* wbt   = (const float*)d_in[9];
    const float* Wih_d = (const float*)d_in[10];
    const float* Whh_d = (const float*)d_in[11];
    const float* bih_d = (const float*)d_in[12];
    const float* bhh_d = (const float*)d_in[13];
    const float* WbW   = (const float*)d_in[14];
    const float* Wbb   = (const float*)d_in[15];
    const float* vbW   = (const float*)d_in[16];
    const float* vbb   = (const float*)d_in[17];
    float* out = (float*)d_out;

    k_init<<<256, 256>>>();
    k_xp<<<256, 128>>>(inp, WU_e);

    for (int s = 0; s < 64; ++s) {
        int par = s & 1;
        k_enc_att<<<256, 128>>>(inp, WU_e, v_e, s, par);
        k_enc_gates<<<dim3(8, 16), 128>>>(Wih_e, Whh_e, bih_e, bhh_e, s, par);
    }

    k_xd<<<dim3(256, 4), 256>>>(WU_d);
    k_init<<<256, 256>>>();

    for (int s = 0; s < 63; ++s) {
        int par = s & 1;
        k_dec_hsw<<<dim3(16, 8), 128>>>(WU_d, par);
        k_dec_att<<<256, 256>>>(inp, v_d, wbt, s, par);
        k_dec_gates<<<dim3(8, 16), 128>>>(Wih_d, Whh_d, bih_d, bhh_d, par);
    }

    // after 63 decoder steps, final h/c live in parity (63 & 1) = 1
    k_final<<<256, 256>>>(WbW, Wbb, vbW, vbb, out, 1);
}

// round 2
// speedup vs baseline: 1.5299x; 1.5299x over previous
#include <cuda_runtime.h>
#include <math.h>

#define BB 256
#define TT 64
#define NN 128
#define MM 256
#define INROW 129   // N + YD

// ---------------- scratch (device globals; no allocation) ----------------
__device__ float g_Xp[BB*TT*NN];     // [b][t][n]  precomputed X_nt @ WU_e_x^T
__device__ float g_Xe[BB*TT*MM];     // [b][t][m]  encoder outputs
__device__ float g_Xd[BB*TT*MM];     // [b][t][m]  precomputed Xe @ WU_d_x^T
__device__ float g_h[2][BB*MM];
__device__ float g_c[2][BB*MM];
__device__ float g_xin[BB*NN];
__device__ float g_hsW[BB*MM];
__device__ float g_ctx[BB*MM];
__device__ float g_yt[BB];

__device__ __forceinline__ float fast_sigm(float x) {
    return __fdividef(1.0f, 1.0f + __expf(-x));
}
__device__ __forceinline__ float fast_tanh(float x) {
    float e = __expf(2.0f * x);
    return 1.0f - __fdividef(2.0f, e + 1.0f);
}

__device__ __forceinline__ float wredsum(float v) {
    #pragma unroll
    for (int o = 16; o > 0; o >>= 1) v += __shfl_down_sync(0xffffffffu, v, o);
    return v;
}
__device__ __forceinline__ float wredmax(float v) {
    #pragma unroll
    for (int o = 16; o > 0; o >>= 1) v = fmaxf(v, __shfl_down_sync(0xffffffffu, v, o));
    return v;
}

// ---------------- init: zero state buffers ----------------
__global__ void k_init() {
    int idx = blockIdx.x * blockDim.x + threadIdx.x;  // 256*256 = 65536 = BB*MM
    g_h[0][idx] = 0.f; g_h[1][idx] = 0.f;
    g_c[0][idx] = 0.f; g_c[1][idx] = 0.f;
}

// ---------------- precompute Xp[b][t][n] = sum_tp X[b,tp,n] * WU_e[t, 512+tp] ----------------
__global__ void k_xp(const float* __restrict__ inp, const float* __restrict__ WU_e) {
    __shared__ float WUx[64*64];   // [t][tp]
    __shared__ float Xs[64*128];   // [tp][n]
    int b = blockIdx.x;
    int tid = threadIdx.x;  // 128
    for (int idx = tid; idx < 4096; idx += 128) {
        int t = idx >> 6, tp = idx & 63;
        WUx[idx] = WU_e[t*576 + 512 + tp];
    }
    for (int idx = tid; idx < 8192; idx += 128) {
        int tp = idx >> 7, n = idx & 127;
        Xs[idx] = inp[b*TT*INROW + tp*INROW + n];
    }
    __syncthreads();
    float acc[64];
    #pragma unroll
    for (int t = 0; t < 64; ++t) acc[t] = 0.f;
    int n = tid;
    for (int tp = 0; tp < 64; ++tp) {
        float xv = Xs[tp*128 + n];
        #pragma unroll
        for (int t = 0; t < 64; ++t) acc[t] += xv * WUx[t*64 + tp];
    }
    #pragma unroll
    for (int t = 0; t < 64; ++t) g_Xp[(b*TT + t)*NN + n] = acc[t];
}

// ---------------- encoder attention (per step): hsW + E + softmax + x*alpha ----------------
__global__ void k_enc_att(const float* __restrict__ inp, const float* __restrict__ WU_e,
                          const float* __restrict__ v_e, int step, int par) {
    int b = blockIdx.x;
    int tid = threadIdx.x;          // 128
    int w = tid >> 5, l = tid & 31;
    __shared__ float hs[512];
    __shared__ float hsW_s[64];
    __shared__ float ves[64];
    __shared__ float redm[4], reds[4];
    const float* hb = g_h[par] + b*MM;
    const float* cb = g_c[par] + b*MM;
    hs[tid]       = hb[tid];
    hs[tid + 128] = hb[tid + 128];
    hs[tid + 256] = cb[tid];
    hs[tid + 384] = cb[tid + 128];
    if (tid < 64) ves[tid] = v_e[tid];
    __syncthreads();
    // hsW[t] = sum_k hs[k] * WU_e[t,k], t handled warp-wise
    for (int t = w*16; t < w*16 + 16; ++t) {
        const float* row = WU_e + t*576;
        float s = 0.f;
        #pragma unroll
        for (int k = l; k < 512; k += 32) s += hs[k] * row[k];
        s = wredsum(s);
        if (l == 0) hsW_s[t] = s;
    }
    __syncthreads();
    int n = tid;
    float e = 0.f;
    const float* xp = g_Xp + b*TT*NN + n;
    #pragma unroll 8
    for (int t = 0; t < 64; ++t) e += ves[t] * fast_tanh(hsW_s[t] + xp[t*NN]);
    // softmax over n (128 threads)
    float m = wredmax(e);
    if (l == 0) redm[w] = m;
    __syncthreads();
    m = fmaxf(fmaxf(redm[0], redm[1]), fmaxf(redm[2], redm[3]));
    float p = __expf(e - m);
    float s = wredsum(p);
    if (l == 0) reds[w] = s;
    __syncthreads();
    float tot = reds[0] + reds[1] + reds[2] + reds[3];
    float alpha = __fdividef(p, tot);
    g_xin[b*NN + n] = inp[b*TT*INROW + step*INROW + n] * alpha;
}

// ---------------- encoder gates GEMM + fused LSTM ----------------
// grid (8, 16): tile 32 batch x 64 gate-cols. 256 threads = 2 K-groups of 128.
// Each K-group covers 192 of K=384 (6 chunks of 32), 4x4 micro-tile per thread.
__global__ void __launch_bounds__(256) k_enc_gates(
        const float* __restrict__ Wih, const float* __restrict__ Whh,
        const float* __restrict__ bih, const float* __restrict__ bhh,
        int step, int par) {
    int bb = blockIdx.x, mo = blockIdx.y;
    int tid = threadIdx.x;
    int kg = tid >> 7;            // 0 or 1
    int t128 = tid & 127;
    int ty = t128 >> 4, tx = t128 & 15;
    __shared__ float A_s[2][32][36];
    __shared__ float W_s[2][32][68];
    __shared__ float red[32][65];
    float acc[4][4];
    #pragma unroll
    for (int i = 0; i < 4; ++i)
        #pragma unroll
        for (int j = 0; j < 4; ++j) acc[i][j] = 0.f;
    const float* hsrc = g_h[par];
    int kbase = kg * 192;
    for (int c = 0; c < 6; ++c) {
        int kc = kbase + c*32;
        for (int idx = t128; idx < 1024; idx += 128) {
            int bi = idx >> 5, kk = idx & 31;
            int k = kc + kk, gb = bb*32 + bi;
            A_s[kg][kk][bi] = (k < 128) ? g_xin[gb*NN + k] : hsrc[gb*MM + (k - 128)];
        }
        for (int idx = t128; idx < 2048; idx += 128) {
            int co = idx >> 5, kk = idx & 31;
            int row = (co >> 4)*256 + mo*16 + (co & 15);
            int k = kc + kk;
            W_s[kg][kk][co] = (k < 128) ? Wih[row*128 + k] : Whh[row*256 + (k - 128)];
        }
        __syncthreads();
        #pragma unroll
        for (int kk = 0; kk < 32; ++kk) {
            float4 a = *(const float4*)&A_s[kg][kk][ty*4];
            float4 w = *(const float4*)&W_s[kg][kk][tx*4];
            acc[0][0] += a.x*w.x; acc[0][1] += a.x*w.y; acc[0][2] += a.x*w.z; acc[0][3] += a.x*w.w;
            acc[1][0] += a.y*w.x; acc[1][1] += a.y*w.y; acc[1][2] += a.y*w.z; acc[1][3] += a.y*w.w;
            acc[2][0] += a.z*w.x; acc[2][1] += a.z*w.y; acc[2][2] += a.z*w.z; acc[2][3] += a.z*w.w;
            acc[3][0] += a.w*w.x; acc[3][1] += a.w*w.y; acc[3][2] += a.w*w.z; acc[3][3] += a.w*w.w;
        }
        __syncthreads();
    }
    // combine the two K-group partials in smem
    if (kg == 0) {
        #pragma unroll
        for (int i = 0; i < 4; ++i)
            #pragma unroll
            for (int j = 0; j < 4; ++j) red[ty*4 + i][tx*4 + j] = acc[i][j];
    }
    __syncthreads();
    if (kg == 1) {
        #pragma unroll
        for (int i = 0; i < 4; ++i)
            #pragma unroll
            for (int j = 0; j < 4; ++j) red[ty*4 + i][tx*4 + j] += acc[i][j];
    }
    __syncthreads();
    // fused LSTM epilogue: 512 (b,m) pairs over 256 threads
    for (int p = tid; p < 512; p += 256) {
        int bi = p >> 4, ml = p & 15;
        int gb = bb*32 + bi, m = mo*16 + ml;
        float gi = red[bi][ml]      + bih[m]       + bhh[m];
        float gf = red[bi][16 + ml] + bih[256 + m] + bhh[256 + m];
        float gg = red[bi][32 + ml] + bih[512 + m] + bhh[512 + m];
        float go = red[bi][48 + ml] + bih[768 + m] + bhh[768 + m];
        float cold = g_c[par][gb*MM + m];
        float cn = fast_sigm(gf)*cold + fast_sigm(gi)*fast_tanh(gg);
        float hn = fast_sigm(go)*fast_tanh(cn);
        g_c[par ^ 1][gb*MM + m] = cn;
        g_h[par ^ 1][gb*MM + m] = hn;
        g_Xe[(gb*TT + step)*MM + m] = hn;
    }
}

// ---------------- precompute Xd[b][t][m] = sum_k Xe[b,t,k] * WU_d[m, 512+k] ----------------
// rows R = b*64+t (16384), tiled 64x64, grid (256, 4), 256 threads 4x4/thread
__global__ void k_xd(const float* __restrict__ WU_d) {
    int rb = blockIdx.x, ob = blockIdx.y;
    int tid = threadIdx.x;
    int ty = tid >> 4, tx = tid & 15;
    __shared__ float A_s[32][68];
    __shared__ float W_s[32][68];
    float acc[4][4];
    #pragma unroll
    for (int i = 0; i < 4; ++i)
        #pragma unroll
        for (int j = 0; j < 4; ++j) acc[i][j] = 0.f;
    for (int kc = 0; kc < 256; kc += 32) {
        for (int idx = tid; idx < 2048; idx += 256) {
            int ri = idx >> 5, kk = idx & 31;
            A_s[kk][ri] = g_Xe[(rb*64 + ri)*MM + kc + kk];
        }
        for (int idx = tid; idx < 2048; idx += 256) {
            int co = idx >> 5, kk = idx & 31;
            W_s[kk][co] = WU_d[(ob*64 + co)*768 + 512 + kc + kk];
        }
        __syncthreads();
        #pragma unroll
        for (int kk = 0; kk < 32; ++kk) {
            float4 a = *(const float4*)&A_s[kk][ty*4];
            float4 w = *(const float4*)&W_s[kk][tx*4];
            acc[0][0] += a.x*w.x; acc[0][1] += a.x*w.y; acc[0][2] += a.x*w.z; acc[0][3] += a.x*w.w;
            acc[1][0] += a.y*w.x; acc[1][1] += a.y*w.y; acc[1][2] += a.y*w.z; acc[1][3] += a.y*w.w;
            acc[2][0] += a.z*w.x; acc[2][1] += a.z*w.y; acc[2][2] += a.z*w.z; acc[2][3] += a.z*w.w;
            acc[3][0] += a.w*w.x; acc[3][1] += a.w*w.y; acc[3][2] += a.w*w.z; acc[3][3] += a.w*w.w;
        }
        __syncthreads();
    }
    #pragma unroll
    for (int i = 0; i < 4; ++i)
        #pragma unroll
        for (int j = 0; j < 4; ++j)
            g_Xd[(rb*64 + ty*4 + i)*MM + ob*64 + tx*4 + j] = acc[i][j];
}

// ---------------- decoder hsW GEMM: (B,512)[h|c] @ WU_d[:, :512]^T -> (B,256) ----------------
// grid (16, 8), tile 16b x 32o, 256 threads = 2 K-groups of 128, 2x2/thread
__global__ void __launch_bounds__(256) k_dec_hsw(const float* __restrict__ WU_d, int par) {
    int rb = blockIdx.x, ob = blockIdx.y;
    int tid = threadIdx.x;
    int kg = tid >> 7;
    int t128 = tid & 127;
    int ty = t128 >> 4, tx = t128 & 15;
    __shared__ float A_s[2][32][20];
    __shared__ float W_s[2][32][36];
    __shared__ float red[16][33];
    float a00 = 0.f, a01 = 0.f, a10 = 0.f, a11 = 0.f;
    int kbase = kg * 256;
    for (int c = 0; c < 8; ++c) {
        int kc = kbase + c*32;
        for (int idx = t128; idx < 512; idx += 128) {
            int ri = idx >> 5, kk = idx & 31;
            int k = kc + kk, gb = rb*16 + ri;
            A_s[kg][kk][ri] = (k < 256) ? g_h[par][gb*MM + k] : g_c[par][gb*MM + k - 256];
        }
        for (int idx = t128; idx < 1024; idx += 128) {
            int co = idx >> 5, kk = idx & 31;
            W_s[kg][kk][co] = WU_d[(ob*32 + co)*768 + kc + kk];
        }
        __syncthreads();
        #pragma unroll
        for (int kk = 0; kk < 32; ++kk) {
            float2 a = *(const float2*)&A_s[kg][kk][ty*2];
            float2 w = *(const float2*)&W_s[kg][kk][tx*2];
            a00 += a.x*w.x; a01 += a.x*w.y; a10 += a.y*w.x; a11 += a.y*w.y;
        }
        __syncthreads();
    }
    if (kg == 0) {
        red[ty*2][tx*2] = a00;     red[ty*2][tx*2 + 1] = a01;
        red[ty*2 + 1][tx*2] = a10; red[ty*2 + 1][tx*2 + 1] = a11;
    }
    __syncthreads();
    if (kg == 1) {
        red[ty*2][tx*2] += a00;     red[ty*2][tx*2 + 1] += a01;
        red[ty*2 + 1][tx*2] += a10; red[ty*2 + 1][tx*2 + 1] += a11;
    }
    __syncthreads();
    for (int p = tid; p < 512; p += 256) {
        int ri = p >> 5, co = p & 31;
        g_hsW[(rb*16 + ri)*MM + ob*32 + co] = red[ri][co];
    }
}

// ---------------- decoder attention: l, beta, ctx, y_tilde ----------------
__global__ void k_dec_att(const float* __restrict__ inp, const float* __restrict__ v_d,
                          const float* __restrict__ wbt, int step, int par) {
    int b = blockIdx.x;
    int tid = threadIdx.x;   // 256
    int w = tid >> 5, l = tid & 31;
    __shared__ float hsw_s[256], vds[256], l_s[64], beta_s[64], reds[8];
    hsw_s[tid] = g_hsW[b*MM + tid];
    vds[tid] = v_d[tid];
    __syncthreads();
    for (int t = w; t < 64; t += 8) {
        const float* xd = g_Xd + (b*TT + t)*MM;
        float s = 0.f;
        #pragma unroll
        for (int m = l; m < 256; m += 32) s += vds[m] * fast_tanh(hsw_s[m] + xd[m]);
        s = wredsum(s);
        if (l == 0) l_s[t] = s;
    }
    __syncthreads();
    if (tid < 32) {
        float a0 = l_s[tid], a1 = l_s[tid + 32];
        float mx = wredmax(fmaxf(a0, a1));
        mx = __shfl_sync(0xffffffffu, mx, 0);
        float p0 = __expf(a0 - mx), p1 = __expf(a1 - mx);
        float sm = wredsum(p0 + p1);
        sm = __shfl_sync(0xffffffffu, sm, 0);
        beta_s[tid] = __fdividef(p0, sm);
        beta_s[tid + 32] = __fdividef(p1, sm);
    }
    __syncthreads();
    float c = 0.f;
    const float* xe = g_Xe + b*TT*MM + tid;
    #pragma unroll 8
    for (int t = 0; t < 64; ++t) c += beta_s[t] * xe[t*MM];
    g_ctx[b*MM + tid] = c;
    float part = wbt[1 + tid] * c;
    part = wredsum(part);
    if (l == 0) reds[w] = part;
    __syncthreads();
    if (tid == 0) {
        float tot = 0.f;
        #pragma unroll
        for (int i = 0; i < 8; ++i) tot += reds[i];
        g_yt[b] = wbt[0] * inp[b*TT*INROW + step*INROW + 128] + tot;
    }
}

// ---------------- decoder gates GEMM (K=256) + fused LSTM ----------------
// grid (8, 16), 256 threads = 2 K-groups of 128 (each 128 of K, 4 chunks)
__global__ void __launch_bounds__(256) k_dec_gates(
        const float* __restrict__ Wihd, const float* __restrict__ Whh,
        const float* __restrict__ bih, const float* __restrict__ bhh,
        int par) {
    int bb = blockIdx.x, mo = blockIdx.y;
    int tid = threadIdx.x;
    int kg = tid >> 7;
    int t128 = tid & 127;
    int ty = t128 >> 4, tx = t128 & 15;
    __shared__ float A_s[2][32][36];
    __shared__ float W_s[2][32][68];
    __shared__ float red[32][65];
    float acc[4][4];
    #pragma unroll
    for (int i = 0; i < 4; ++i)
        #pragma unroll
        for (int j = 0; j < 4; ++j) acc[i][j] = 0.f;
    const float* hsrc = g_h[par];
    int kbase = kg * 128;
    for (int c = 0; c < 4; ++c) {
        int kc = kbase + c*32;
        for (int idx = t128; idx < 1024; idx += 128) {
            int bi = idx >> 5, kk = idx & 31;
            A_s[kg][kk][bi] = hsrc[(bb*32 + bi)*MM + kc + kk];
        }
        for (int idx = t128; idx < 2048; idx += 128) {
            int co = idx >> 5, kk = idx & 31;
            int row = (co >> 4)*256 + mo*16 + (co & 15);
            W_s[kg][kk][co] = Whh[row*256 + kc + kk];
        }
        __syncthreads();
        #pragma unroll
        for (int kk = 0; kk < 32; ++kk) {
            float4 a = *(const float4*)&A_s[kg][kk][ty*4];
            float4 w = *(const float4*)&W_s[kg][kk][tx*4];
            acc[0][0] += a.x*w.x; acc[0][1] += a.x*w.y; acc[0][2] += a.x*w.z; acc[0][3] += a.x*w.w;
            acc[1][0] += a.y*w.x; acc[1][1] += a.y*w.y; acc[1][2] += a.y*w.z; acc[1][3] += a.y*w.w;
            acc[2][0] += a.z*w.x; acc[2][1] += a.z*w.y; acc[2][2] += a.z*w.z; acc[2][3] += a.z*w.w;
            acc[3][0] += a.w*w.x; acc[3][1] += a.w*w.y; acc[3][2] += a.w*w.z; acc[3][3] += a.w*w.w;
        }
        __syncthreads();
    }
    if (kg == 0) {
        #pragma unroll
        for (int i = 0; i < 4; ++i)
            #pragma unroll
            for (int j = 0; j < 4; ++j) red[ty*4 + i][tx*4 + j] = acc[i][j];
    }
    __syncthreads();
    if (kg == 1) {
        #pragma unroll
        for (int i = 0; i < 4; ++i)
            #pragma unroll
            for (int j = 0; j < 4; ++j) red[ty*4 + i][tx*4 + j] += acc[i][j];
    }
    __syncthreads();
    for (int p = tid; p < 512; p += 256) {
        int bi = p >> 4, ml = p & 15;
        int gb = bb*32 + bi, m = mo*16 + ml;
        float yt = g_yt[gb];
        float gi = red[bi][ml]      + bih[m]       + bhh[m]       + yt*Wihd[m];
        float gf = red[bi][16 + ml] + bih[256 + m] + bhh[256 + m] + yt*Wihd[256 + m];
        float gg = red[bi][32 + ml] + bih[512 + m] + bhh[512 + m] + yt*Wihd[512 + m];
        float go = red[bi][48 + ml] + bih[768 + m] + bhh[768 + m] + yt*Wihd[768 + m];
        float cold = g_c[par][gb*MM + m];
        float cn = fast_sigm(gf)*cold + fast_sigm(gi)*fast_tanh(gg);
        float hn = fast_sigm(go)*fast_tanh(cn);
        g_c[par ^ 1][gb*MM + m] = cn;
        g_h[par ^ 1][gb*MM + m] = hn;
    }
}

// ---------------- final projection ----------------
__global__ void k_final(const float* __restrict__ WbW, const float* __restrict__ Wbb,
                        const float* __restrict__ vbW, const float* __restrict__ vbb,
                        float* __restrict__ out, int par) {
    int b = blockIdx.x;
    int tid = threadIdx.x;   // 256
    int w = tid >> 5, l = tid & 31;
    __shared__ float hc[512];
    __shared__ float hid[256];
    __shared__ float reds[8];
    hc[tid]       = g_h[par][b*MM + tid];
    hc[256 + tid] = g_ctx[b*MM + tid];
    __syncthreads();
    for (int p = w*32; p < w*32 + 32; ++p) {
        const float* row = WbW + p*512;
        float s = 0.f;
        #pragma unroll
        for (int k = l; k < 512; k += 32) s += hc[k] * row[k];
        s = wredsum(s);
        if (l == 0) hid[p] = s + Wbb[p];
    }
    __syncthreads();
    float part = hid[tid] * vbW[tid];
    part = wredsum(part);
    if (l == 0) reds[w] = part;
    __syncthreads();
    if (tid == 0) {
        float tot = 0.f;
        #pragma unroll
        for (int i = 0; i < 8; ++i) tot += reds[i];
        out[b] = tot + vbb[0];
    }
}

// ---------------- launcher ----------------
extern "C" void kernel_launch(void* const* d_in, const int* in_sizes, int n_in,
                              void* d_out, int out_size) {
    const float* inp   = (const float*)d_in[0];
    const float* WU_e  = (const float*)d_in[1];
    const float* v_e   = (const float*)d_in[2];
    const float* Wih_e = (const float*)d_in[3];
    const float* Whh_e = (const float*)d_in[4];
    const float* bih_e = (const float*)d_in[5];
    const float* bhh_e = (const float*)d_in[6];
    const float* WU_d  = (const float*)d_in[7];
    const float* v_d   = (const float*)d_in[8];
    const float* wbt   = (const float*)d_in[9];
    const float* Wih_d = (const float*)d_in[10];
    const float* Whh_d = (const float*)d_in[11];
    const float* bih_d = (const float*)d_in[12];
    const float* bhh_d = (const float*)d_in[13];
    const float* WbW   = (const float*)d_in[14];
    const float* Wbb   = (const float*)d_in[15];
    const float* vbW   = (const float*)d_in[16];
    const float* vbb   = (const float*)d_in[17];
    float* out = (float*)d_out;

    k_init<<<256, 256>>>();
    k_xp<<<256, 128>>>(inp, WU_e);

    for (int s = 0; s < 64; ++s) {
        int par = s & 1;
        k_enc_att<<<256, 128>>>(inp, WU_e, v_e, s, par);
        k_enc_gates<<<dim3(8, 16), 256>>>(Wih_e, Whh_e, bih_e, bhh_e, s, par);
    }

    k_xd<<<dim3(256, 4), 256>>>(WU_d);
    k_init<<<256, 256>>>();

    for (int s = 0; s < 63; ++s) {
        int par = s & 1;
        k_dec_hsw<<<dim3(16, 8), 256>>>(WU_d, par);
        k_dec_att<<<256, 256>>>(inp, v_d, wbt, s, par);
        k_dec_gates<<<dim3(8, 16), 256>>>(Wih_d, Whh_d, bih_d, bhh_d, par);
    }

    // after 63 decoder steps, final h/c live in parity (63 & 1) = 1
    k_final<<<256, 256>>>(WbW, Wbb, vbW, vbb, out, 1);
}

// round 3
// speedup vs baseline: 1.7323x; 1.1323x over previous
#include <cuda_runtime.h>
#include <math.h>

#define BB 256
#define TT 64
#define NN 128
#define MM 256
#define INROW 129   // N + YD

// ---------------- scratch (device globals; no allocation) ----------------
__device__ float g_Xp[BB*TT*NN];     // [b][t][n]  precomputed X_nt @ WU_e_x^T
__device__ float g_Xe[BB*TT*MM];     // [b][t][m]  encoder outputs
__device__ float g_Xd[BB*TT*MM];     // [b][t][m]  precomputed Xe @ WU_d_x^T
__device__ float g_h[2][BB*MM];
__device__ float g_c[2][BB*MM];
__device__ float g_xin[BB*NN];
__device__ float g_hsW[BB*MM];
__device__ float g_ctx[BB*MM];
__device__ float g_yt[BB];

__device__ __forceinline__ float fast_sigm(float x) {
    return __fdividef(1.0f, 1.0f + __expf(-x));
}
__device__ __forceinline__ float fast_tanh(float x) {
    float e = __expf(2.0f * x);
    return 1.0f - __fdividef(2.0f, e + 1.0f);
}

__device__ __forceinline__ float wredsum(float v) {
    #pragma unroll
    for (int o = 16; o > 0; o >>= 1) v += __shfl_down_sync(0xffffffffu, v, o);
    return v;
}
__device__ __forceinline__ float wredmax(float v) {
    #pragma unroll
    for (int o = 16; o > 0; o >>= 1) v = fmaxf(v, __shfl_down_sync(0xffffffffu, v, o));
    return v;
}

// ---------------- init: zero state buffers ----------------
__global__ void k_init() {
    int idx = blockIdx.x * blockDim.x + threadIdx.x;  // 256*256 = 65536 = BB*MM
    g_h[0][idx] = 0.f; g_h[1][idx] = 0.f;
    g_c[0][idx] = 0.f; g_c[1][idx] = 0.f;
}

// ---------------- precompute Xp[b][t][n] = sum_tp X[b,tp,n] * WU_e[t, 512+tp] ----------------
__global__ void k_xp(const float* __restrict__ inp, const float* __restrict__ WU_e) {
    __shared__ float WUx[64*64];   // [t][tp]
    __shared__ float Xs[64*128];   // [tp][n]
    int b = blockIdx.x;
    int tid = threadIdx.x;  // 128
    for (int idx = tid; idx < 4096; idx += 128) {
        int t = idx >> 6, tp = idx & 63;
        WUx[idx] = WU_e[t*576 + 512 + tp];
    }
    for (int idx = tid; idx < 8192; idx += 128) {
        int tp = idx >> 7, n = idx & 127;
        Xs[idx] = inp[b*TT*INROW + tp*INROW + n];
    }
    __syncthreads();
    float acc[64];
    #pragma unroll
    for (int t = 0; t < 64; ++t) acc[t] = 0.f;
    int n = tid;
    for (int tp = 0; tp < 64; ++tp) {
        float xv = Xs[tp*128 + n];
        #pragma unroll
        for (int t = 0; t < 64; ++t) acc[t] += xv * WUx[t*64 + tp];
    }
    #pragma unroll
    for (int t = 0; t < 64; ++t) g_Xp[(b*TT + t)*NN + n] = acc[t];
}

// ---------------- encoder attention (per step): hsW + E + softmax + x*alpha ----------------
__global__ void k_enc_att(const float* __restrict__ inp, const float* __restrict__ WU_e,
                          const float* __restrict__ v_e, int step, int par) {
    int b = blockIdx.x;
    int tid = threadIdx.x;          // 128
    int w = tid >> 5, l = tid & 31;
    __shared__ float hs[512];
    __shared__ float hsW_s[64];
    __shared__ float ves[64];
    __shared__ float redm[4], reds[4];
    const float* hb = g_h[par] + b*MM;
    const float* cb = g_c[par] + b*MM;
    hs[tid]       = hb[tid];
    hs[tid + 128] = hb[tid + 128];
    hs[tid + 256] = cb[tid];
    hs[tid + 384] = cb[tid + 128];
    if (tid < 64) ves[tid] = v_e[tid];
    __syncthreads();
    // hsW[t] = sum_k hs[k] * WU_e[t,k], t handled warp-wise
    for (int t = w*16; t < w*16 + 16; ++t) {
        const float* row = WU_e + t*576;
        float s = 0.f;
        #pragma unroll
        for (int k = l; k < 512; k += 32) s += hs[k] * row[k];
        s = wredsum(s);
        if (l == 0) hsW_s[t] = s;
    }
    __syncthreads();
    int n = tid;
    float e = 0.f;
    const float* xp = g_Xp + b*TT*NN + n;
    #pragma unroll 8
    for (int t = 0; t < 64; ++t) e += ves[t] * fast_tanh(hsW_s[t] + xp[t*NN]);
    // softmax over n (128 threads)
    float m = wredmax(e);
    if (l == 0) redm[w] = m;
    __syncthreads();
    m = fmaxf(fmaxf(redm[0], redm[1]), fmaxf(redm[2], redm[3]));
    float p = __expf(e - m);
    float s = wredsum(p);
    if (l == 0) reds[w] = s;
    __syncthreads();
    float tot = reds[0] + reds[1] + reds[2] + reds[3];
    float alpha = __fdividef(p, tot);
    g_xin[b*NN + n] = inp[b*TT*INROW + step*INROW + n] * alpha;
}

// ---------------- encoder gates GEMM + fused LSTM ----------------
// grid (16, 16): tile 16 batch x 64 gate-cols. 256 threads = 2 K-groups of 128.
// Each K-group covers 192 of K=384 (6 chunks of 32), 2x4 micro-tile per thread.
__global__ void __launch_bounds__(256) k_enc_gates(
        const float* __restrict__ Wih, const float* __restrict__ Whh,
        const float* __restrict__ bih, const float* __restrict__ bhh,
        int step, int par) {
    int bb = blockIdx.x, mo = blockIdx.y;
    int tid = threadIdx.x;
    int kg = tid >> 7;            // 0 or 1
    int t128 = tid & 127;
    int ty = t128 >> 4, tx = t128 & 15;    // ty: 0..7 (2 rows each), tx: 0..15 (4 cols)
    __shared__ float A_s[2][32][20];
    __shared__ float W_s[2][32][68];
    __shared__ float red[16][65];
    float acc[2][4];
    #pragma unroll
    for (int i = 0; i < 2; ++i)
        #pragma unroll
        for (int j = 0; j < 4; ++j) acc[i][j] = 0.f;
    const float* hsrc = g_h[par];
    int kbase = kg * 192;

    // prefetch chunk 0
    float ra[4], rw[16];
    {
        int kc = kbase;
        #pragma unroll
        for (int u = 0; u < 4; ++u) {
            int idx = t128 + u*128;
            int row = idx >> 5, kk = idx & 31;
            int k = kc + kk, gb = bb*16 + row;
            ra[u] = (k < 128) ? g_xin[gb*NN + k] : hsrc[gb*MM + (k - 128)];
        }
        #pragma unroll
        for (int u = 0; u < 16; ++u) {
            int idx = t128 + u*128;
            int co = idx >> 5, kk = idx & 31;
            int row = (co >> 4)*256 + mo*16 + (co & 15);
            int k = kc + kk;
            rw[u] = (k < 128) ? Wih[row*128 + k] : Whh[row*256 + (k - 128)];
        }
    }

    for (int c = 0; c < 6; ++c) {
        // store prefetched chunk to smem
        #pragma unroll
        for (int u = 0; u < 4; ++u) {
            int idx = t128 + u*128;
            A_s[kg][idx & 31][idx >> 5] = ra[u];
        }
        #pragma unroll
        for (int u = 0; u < 16; ++u) {
            int idx = t128 + u*128;
            W_s[kg][idx & 31][idx >> 5] = rw[u];
        }
        __syncthreads();
        // prefetch next chunk while computing
        if (c < 5) {
            int kc = kbase + (c + 1)*32;
            #pragma unroll
            for (int u = 0; u < 4; ++u) {
                int idx = t128 + u*128;
                int row = idx >> 5, kk = idx & 31;
                int k = kc + kk, gb = bb*16 + row;
                ra[u] = (k < 128) ? g_xin[gb*NN + k] : hsrc[gb*MM + (k - 128)];
            }
            #pragma unroll
            for (int u = 0; u < 16; ++u) {
                int idx = t128 + u*128;
                int co = idx >> 5, kk = idx & 31;
                int row = (co >> 4)*256 + mo*16 + (co & 15);
                int k = kc + kk;
                rw[u] = (k < 128) ? Wih[row*128 + k] : Whh[row*256 + (k - 128)];
            }
        }
        #pragma unroll
        for (int kk = 0; kk < 32; ++kk) {
            float2 a = *(const float2*)&A_s[kg][kk][ty*2];
            float4 w = *(const float4*)&W_s[kg][kk][tx*4];
            acc[0][0] += a.x*w.x; acc[0][1] += a.x*w.y; acc[0][2] += a.x*w.z; acc[0][3] += a.x*w.w;
            acc[1][0] += a.y*w.x; acc[1][1] += a.y*w.y; acc[1][2] += a.y*w.z; acc[1][3] += a.y*w.w;
        }
        __syncthreads();
    }
    // combine the two K-group partials in smem
    if (kg == 0) {
        #pragma unroll
        for (int i = 0; i < 2; ++i)
            #pragma unroll
            for (int j = 0; j < 4; ++j) red[ty*2 + i][tx*4 + j] = acc[i][j];
    }
    __syncthreads();
    if (kg == 1) {
        #pragma unroll
        for (int i = 0; i < 2; ++i)
            #pragma unroll
            for (int j = 0; j < 4; ++j) red[ty*2 + i][tx*4 + j] += acc[i][j];
    }
    __syncthreads();
    // fused LSTM epilogue: 256 (b,m) pairs over 256 threads
    {
        int bi = tid >> 4, ml = tid & 15;
        int gb = bb*16 + bi, m = mo*16 + ml;
        float gi = red[bi][ml]      + bih[m]       + bhh[m];
        float gf = red[bi][16 + ml] + bih[256 + m] + bhh[256 + m];
        float gg = red[bi][32 + ml] + bih[512 + m] + bhh[512 + m];
        float go = red[bi][48 + ml] + bih[768 + m] + bhh[768 + m];
        float cold = g_c[par][gb*MM + m];
        float cn = fast_sigm(gf)*cold + fast_sigm(gi)*fast_tanh(gg);
        float hn = fast_sigm(go)*fast_tanh(cn);
        g_c[par ^ 1][gb*MM + m] = cn;
        g_h[par ^ 1][gb*MM + m] = hn;
        g_Xe[(gb*TT + step)*MM + m] = hn;
    }
}

// ---------------- precompute Xd[b][t][m] = sum_k Xe[b,t,k] * WU_d[m, 512+k] ----------------
// rows R = b*64+t (16384), tiled 64x64, grid (256, 4), 256 threads 4x4/thread
__global__ void k_xd(const float* __restrict__ WU_d) {
    int rb = blockIdx.x, ob = blockIdx.y;
    int tid = threadIdx.x;
    int ty = tid >> 4, tx = tid & 15;
    __shared__ float A_s[32][68];
    __shared__ float W_s[32][68];
    float acc[4][4];
    #pragma unroll
    for (int i = 0; i < 4; ++i)
        #pragma unroll
        for (int j = 0; j < 4; ++j) acc[i][j] = 0.f;
    for (int kc = 0; kc < 256; kc += 32) {
        for (int idx = tid; idx < 2048; idx += 256) {
            int ri = idx >> 5, kk = idx & 31;
            A_s[kk][ri] = g_Xe[(rb*64 + ri)*MM + kc + kk];
        }
        for (int idx = tid; idx < 2048; idx += 256) {
            int co = idx >> 5, kk = idx & 31;
            W_s[kk][co] = WU_d[(ob*64 + co)*768 + 512 + kc + kk];
        }
        __syncthreads();
        #pragma unroll
        for (int kk = 0; kk < 32; ++kk) {
            float4 a = *(const float4*)&A_s[kk][ty*4];
            float4 w = *(const float4*)&W_s[kk][tx*4];
            acc[0][0] += a.x*w.x; acc[0][1] += a.x*w.y; acc[0][2] += a.x*w.z; acc[0][3] += a.x*w.w;
            acc[1][0] += a.y*w.x; acc[1][1] += a.y*w.y; acc[1][2] += a.y*w.z; acc[1][3] += a.y*w.w;
            acc[2][0] += a.z*w.x; acc[2][1] += a.z*w.y; acc[2][2] += a.z*w.z; acc[2][3] += a.z*w.w;
            acc[3][0] += a.w*w.x; acc[3][1] += a.w*w.y; acc[3][2] += a.w*w.z; acc[3][3] += a.w*w.w;
        }
        __syncthreads();
    }
    #pragma unroll
    for (int i = 0; i < 4; ++i)
        #pragma unroll
        for (int j = 0; j < 4; ++j)
            g_Xd[(rb*64 + ty*4 + i)*MM + ob*64 + tx*4 + j] = acc[i][j];
}

// ---------------- decoder hsW GEMM: (B,512)[h|c] @ WU_d[:, :512]^T -> (B,256) ----------------
// grid (16, 16), tile 16b x 16o, 256 threads = 2 K-groups of 128, 2x1/thread
__global__ void __launch_bounds__(256) k_dec_hsw(const float* __restrict__ WU_d, int par) {
    int rb = blockIdx.x, ob = blockIdx.y;
    int tid = threadIdx.x;
    int kg = tid >> 7;
    int t128 = tid & 127;
    int ty = t128 >> 4, tx = t128 & 15;   // ty: 0..7 (2 rows), tx: 0..15 (1 col)
    __shared__ float A_s[2][32][20];
    __shared__ float W_s[2][32][20];
    __shared__ float red[16][17];
    float a0 = 0.f, a1 = 0.f;
    int kbase = kg * 256;
    for (int c = 0; c < 8; ++c) {
        int kc = kbase + c*32;
        #pragma unroll
        for (int u = 0; u < 4; ++u) {
            int idx = t128 + u*128;
            int ri = idx >> 5, kk = idx & 31;
            int k = kc + kk, gb = rb*16 + ri;
            A_s[kg][kk][ri] = (k < 256) ? g_h[par][gb*MM + k] : g_c[par][gb*MM + k - 256];
        }
        #pragma unroll
        for (int u = 0; u < 4; ++u) {
            int idx = t128 + u*128;
            int co = idx >> 5, kk = idx & 31;
            W_s[kg][kk][co] = WU_d[(ob*16 + co)*768 + kc + kk];
        }
        __syncthreads();
        #pragma unroll
        for (int kk = 0; kk < 32; ++kk) {
            float2 a = *(const float2*)&A_s[kg][kk][ty*2];
            float w = W_s[kg][kk][tx];
            a0 += a.x*w; a1 += a.y*w;
        }
        __syncthreads();
    }
    if (kg == 0) {
        red[ty*2][tx] = a0; red[ty*2 + 1][tx] = a1;
    }
    __syncthreads();
    if (kg == 1) {
        red[ty*2][tx] += a0; red[ty*2 + 1][tx] += a1;
    }
    __syncthreads();
    if (tid < 256) {
        int ri = tid >> 4, co = tid & 15;
        g_hsW[(rb*16 + ri)*MM + ob*16 + co] = red[ri][co];
    }
}

// ---------------- decoder attention: l, beta, ctx, y_tilde ----------------
__global__ void k_dec_att(const float* __restrict__ inp, const float* __restrict__ v_d,
                          const float* __restrict__ wbt, int step, int par) {
    int b = blockIdx.x;
    int tid = threadIdx.x;   // 256
    int w = tid >> 5, l = tid & 31;
    __shared__ float hsw_s[256], vds[256], l_s[64], beta_s[64], reds[8];
    hsw_s[tid] = g_hsW[b*MM + tid];
    vds[tid] = v_d[tid];
    __syncthreads();
    for (int t = w; t < 64; t += 8) {
        const float* xd = g_Xd + (b*TT + t)*MM;
        float s = 0.f;
        #pragma unroll
        for (int m = l; m < 256; m += 32) s += vds[m] * fast_tanh(hsw_s[m] + xd[m]);
        s = wredsum(s);
        if (l == 0) l_s[t] = s;
    }
    __syncthreads();
    if (tid < 32) {
        float a0 = l_s[tid], a1 = l_s[tid + 32];
        float mx = wredmax(fmaxf(a0, a1));
        mx = __shfl_sync(0xffffffffu, mx, 0);
        float p0 = __expf(a0 - mx), p1 = __expf(a1 - mx);
        float sm = wredsum(p0 + p1);
        sm = __shfl_sync(0xffffffffu, sm, 0);
        beta_s[tid] = __fdividef(p0, sm);
        beta_s[tid + 32] = __fdividef(p1, sm);
    }
    __syncthreads();
    float c = 0.f;
    const float* xe = g_Xe + b*TT*MM + tid;
    #pragma unroll 8
    for (int t = 0; t < 64; ++t) c += beta_s[t] * xe[t*MM];
    g_ctx[b*MM + tid] = c;
    float part = wbt[1 + tid] * c;
    part = wredsum(part);
    if (l == 0) reds[w] = part;
    __syncthreads();
    if (tid == 0) {
        float tot = 0.f;
        #pragma unroll
        for (int i = 0; i < 8; ++i) tot += reds[i];
        g_yt[b] = wbt[0] * inp[b*TT*INROW + step*INROW + 128] + tot;
    }
}

// ---------------- decoder gates GEMM (K=256) + fused LSTM ----------------
// grid (16, 16): tile 16 batch x 64 cols, 256 threads = 2 K-groups of 128 (each 128 K)
__global__ void __launch_bounds__(256) k_dec_gates(
        const float* __restrict__ Wihd, const float* __restrict__ Whh,
        const float* __restrict__ bih, const float* __restrict__ bhh,
        int par) {
    int bb = blockIdx.x, mo = blockIdx.y;
    int tid = threadIdx.x;
    int kg = tid >> 7;
    int t128 = tid & 127;
    int ty = t128 >> 4, tx = t128 & 15;
    __shared__ float A_s[2][32][20];
    __shared__ float W_s[2][32][68];
    __shared__ float red[16][65];
    float acc[2][4];
    #pragma unroll
    for (int i = 0; i < 2; ++i)
        #pragma unroll
        for (int j = 0; j < 4; ++j) acc[i][j] = 0.f;
    const float* hsrc = g_h[par];
    int kbase = kg * 128;

    float ra[4], rw[16];
    {
        int kc = kbase;
        #pragma unroll
        for (int u = 0; u < 4; ++u) {
            int idx = t128 + u*128;
            int row = idx >> 5, kk = idx & 31;
            ra[u] = hsrc[(bb*16 + row)*MM + kc + kk];
        }
        #pragma unroll
        for (int u = 0; u < 16; ++u) {
            int idx = t128 + u*128;
            int co = idx >> 5, kk = idx & 31;
            int row = (co >> 4)*256 + mo*16 + (co & 15);
            rw[u] = Whh[row*256 + kc + kk];
        }
    }

    for (int c = 0; c < 4; ++c) {
        #pragma unroll
        for (int u = 0; u < 4; ++u) {
            int idx = t128 + u*128;
            A_s[kg][idx & 31][idx >> 5] = ra[u];
        }
        #pragma unroll
        for (int u = 0; u < 16; ++u) {
            int idx = t128 + u*128;
            W_s[kg][idx & 31][idx >> 5] = rw[u];
        }
        __syncthreads();
        if (c < 3) {
            int kc = kbase + (c + 1)*32;
            #pragma unroll
            for (int u = 0; u < 4; ++u) {
                int idx = t128 + u*128;
                int row = idx >> 5, kk = idx & 31;
                ra[u] = hsrc[(bb*16 + row)*MM + kc + kk];
            }
            #pragma unroll
            for (int u = 0; u < 16; ++u) {
                int idx = t128 + u*128;
                int co = idx >> 5, kk = idx & 31;
                int row = (co >> 4)*256 + mo*16 + (co & 15);
                rw[u] = Whh[row*256 + kc + kk];
            }
        }
        #pragma unroll
        for (int kk = 0; kk < 32; ++kk) {
            float2 a = *(const float2*)&A_s[kg][kk][ty*2];
            float4 w = *(const float4*)&W_s[kg][kk][tx*4];
            acc[0][0] += a.x*w.x; acc[0][1] += a.x*w.y; acc[0][2] += a.x*w.z; acc[0][3] += a.x*w.w;
            acc[1][0] += a.y*w.x; acc[1][1] += a.y*w.y; acc[1][2] += a.y*w.z; acc[1][3] += a.y*w.w;
        }
        __syncthreads();
    }
    if (kg == 0) {
        #pragma unroll
        for (int i = 0; i < 2; ++i)
            #pragma unroll
            for (int j = 0; j < 4; ++j) red[ty*2 + i][tx*4 + j] = acc[i][j];
    }
    __syncthreads();
    if (kg == 1) {
        #pragma unroll
        for (int i = 0; i < 2; ++i)
            #pragma unroll
            for (int j = 0; j < 4; ++j) red[ty*2 + i][tx*4 + j] += acc[i][j];
    }
    __syncthreads();
    {
        int bi = tid >> 4, ml = tid & 15;
        int gb = bb*16 + bi, m = mo*16 + ml;
        float yt = g_yt[gb];
        float gi = red[bi][ml]      + bih[m]       + bhh[m]       + yt*Wihd[m];
        float gf = red[bi][16 + ml] + bih[256 + m] + bhh[256 + m] + yt*Wihd[256 + m];
        float gg = red[bi][32 + ml] + bih[512 + m] + bhh[512 + m] + yt*Wihd[512 + m];
        float go = red[bi][48 + ml] + bih[768 + m] + bhh[768 + m] + yt*Wihd[768 + m];
        float cold = g_c[par][gb*MM + m];
        float cn = fast_sigm(gf)*cold + fast_sigm(gi)*fast_tanh(gg);
        float hn = fast_sigm(go)*fast_tanh(cn);
        g_c[par ^ 1][gb*MM + m] = cn;
        g_h[par ^ 1][gb*MM + m] = hn;
    }
}

// ---------------- final projection ----------------
__global__ void k_final(const float* __restrict__ WbW, const float* __restrict__ Wbb,
                        const float* __restrict__ vbW, const float* __restrict__ vbb,
                        float* __restrict__ out, int par) {
    int b = blockIdx.x;
    int tid = threadIdx.x;   // 256
    int w = tid >> 5, l = tid & 31;
    __shared__ float hc[512];
    __shared__ float hid[256];
    __shared__ float reds[8];
    hc[tid]       = g_h[par][b*MM + tid];
    hc[256 + tid] = g_ctx[b*MM + tid];
    __syncthreads();
    for (int p = w*32; p < w*32 + 32; ++p) {
        const float* row = WbW + p*512;
        float s = 0.f;
        #pragma unroll
        for (int k = l; k < 512; k += 32) s += hc[k] * row[k];
        s = wredsum(s);
        if (l == 0) hid[p] = s + Wbb[p];
    }
    __syncthreads();
    float part = hid[tid] * vbW[tid];
    part = wredsum(part);
    if (l == 0) reds[w] = part;
    __syncthreads();
    if (tid == 0) {
        float tot = 0.f;
        #pragma unroll
        for (int i = 0; i < 8; ++i) tot += reds[i];
        out[b] = tot + vbb[0];
    }
}

// ---------------- launcher ----------------
extern "C" void kernel_launch(void* const* d_in, const int* in_sizes, int n_in,
                              void* d_out, int out_size) {
    const float* inp   = (const float*)d_in[0];
    const float* WU_e  = (const float*)d_in[1];
    const float* v_e   = (const float*)d_in[2];
    const float* Wih_e = (const float*)d_in[3];
    const float* Whh_e = (const float*)d_in[4];
    const float* bih_e = (const float*)d_in[5];
    const float* bhh_e = (const float*)d_in[6];
    const float* WU_d  = (const float*)d_in[7];
    const float* v_d   = (const float*)d_in[8];
    const float* wbt   = (const float*)d_in[9];
    const float* Wih_d = (const float*)d_in[10];
    const float* Whh_d = (const float*)d_in[11];
    const float* bih_d = (const float*)d_in[12];
    const float* bhh_d = (const float*)d_in[13];
    const float* WbW   = (const float*)d_in[14];
    const float* Wbb   = (const float*)d_in[15];
    const float* vbW   = (const float*)d_in[16];
    const float* vbb   = (const float*)d_in[17];
    float* out = (float*)d_out;

    k_init<<<256, 256>>>();
    k_xp<<<256, 128>>>(inp, WU_e);

    for (int s = 0; s < 64; ++s) {
        int par = s & 1;
        k_enc_att<<<256, 128>>>(inp, WU_e, v_e, s, par);
        k_enc_gates<<<dim3(16, 16), 256>>>(Wih_e, Whh_e, bih_e, bhh_e, s, par);
    }

    k_xd<<<dim3(256, 4), 256>>>(WU_d);
    k_init<<<256, 256>>>();

    for (int s = 0; s < 63; ++s) {
        int par = s & 1;
        k_dec_hsw<<<dim3(16, 16), 256>>>(WU_d, par);
        k_dec_att<<<256, 256>>>(inp, v_d, wbt, s, par);
        k_dec_gates<<<dim3(16, 16), 256>>>(Wih_d, Whh_d, bih_d, bhh_d, par);
    }

    // after 63 decoder steps, final h/c live in parity (63 & 1) = 1
    k_final<<<256, 256>>>(WbW, Wbb, vbW, vbb, out, 1);
}

// round 4
// speedup vs baseline: 2.1783x; 1.2574x over previous
#include <cuda_runtime.h>
#include <math.h>

#define BB 256
#define TT 64
#define NN 128
#define MM 256
#define INROW 129   // N + YD

// ---------------- scratch (device globals; no allocation) ----------------
__device__ float g_Xp[BB*TT*NN];     // [b][t][n]  precomputed X_nt @ WU_e_x^T
__device__ float g_Xe[BB*TT*MM];     // [b][t][m]  encoder outputs
__device__ float g_Xd[BB*TT*MM];     // [b][t][m]  precomputed Xe @ WU_d_x^T
__device__ float g_h[2][BB*MM];
__device__ float g_c[2][BB*MM];
__device__ float g_xin[BB*NN];
__device__ float g_hsW[BB*MM];
__device__ float g_ctx[BB*MM];
__device__ float g_yt[BB];

__device__ __forceinline__ float fast_sigm(float x) {
    return __fdividef(1.0f, 1.0f + __expf(-x));
}
__device__ __forceinline__ float fast_tanh(float x) {
    float e = __expf(2.0f * x);
    return 1.0f - __fdividef(2.0f, e + 1.0f);
}

__device__ __forceinline__ float wredsum(float v) {
    #pragma unroll
    for (int o = 16; o > 0; o >>= 1) v += __shfl_down_sync(0xffffffffu, v, o);
    return v;
}
__device__ __forceinline__ float wredmax(float v) {
    #pragma unroll
    for (int o = 16; o > 0; o >>= 1) v = fmaxf(v, __shfl_down_sync(0xffffffffu, v, o));
    return v;
}

// ---------------- cp.async helpers ----------------
__device__ __forceinline__ void cp4(void* dst, const float* src) {
    unsigned d = (unsigned)__cvta_generic_to_shared(dst);
    asm volatile("cp.async.ca.shared.global [%0], [%1], 4;" :: "r"(d), "l"(src));
}
__device__ __forceinline__ void cp_commit() {
    asm volatile("cp.async.commit_group;" ::: "memory");
}
template <int N>
__device__ __forceinline__ void cp_wait() {
    asm volatile("cp.async.wait_group %0;" :: "n"(N) : "memory");
}

// ---------------- init: zero state buffers ----------------
__global__ void k_init() {
    int idx = blockIdx.x * blockDim.x + threadIdx.x;  // 256*256 = 65536 = BB*MM
    g_h[0][idx] = 0.f; g_h[1][idx] = 0.f;
    g_c[0][idx] = 0.f; g_c[1][idx] = 0.f;
}

// ---------------- precompute Xp[b][t][n] = sum_tp X[b,tp,n] * WU_e[t, 512+tp] ----------------
__global__ void k_xp(const float* __restrict__ inp, const float* __restrict__ WU_e) {
    __shared__ float WUx[64*64];   // [t][tp]
    __shared__ float Xs[64*128];   // [tp][n]
    int b = blockIdx.x;
    int tid = threadIdx.x;  // 128
    for (int idx = tid; idx < 4096; idx += 128) {
        int t = idx >> 6, tp = idx & 63;
        WUx[idx] = WU_e[t*576 + 512 + tp];
    }
    for (int idx = tid; idx < 8192; idx += 128) {
        int tp = idx >> 7, n = idx & 127;
        Xs[idx] = inp[b*TT*INROW + tp*INROW + n];
    }
    __syncthreads();
    float acc[64];
    #pragma unroll
    for (int t = 0; t < 64; ++t) acc[t] = 0.f;
    int n = tid;
    for (int tp = 0; tp < 64; ++tp) {
        float xv = Xs[tp*128 + n];
        #pragma unroll
        for (int t = 0; t < 64; ++t) acc[t] += xv * WUx[t*64 + tp];
    }
    #pragma unroll
    for (int t = 0; t < 64; ++t) g_Xp[(b*TT + t)*NN + n] = acc[t];
}

// ---------------- encoder attention (per step): hsW + E + softmax + x*alpha ----------------
// 256 threads: hsW over 8 warps (8 rows each); E split in two t-halves.
__global__ void __launch_bounds__(256) k_enc_att(
        const float* __restrict__ inp, const float* __restrict__ WU_e,
        const float* __restrict__ v_e, int step, int par) {
    int b = blockIdx.x;
    int tid = threadIdx.x;          // 256
    int w = tid >> 5, l = tid & 31;
    __shared__ float hs[512];
    __shared__ float hsW_s[64];
    __shared__ float ves[64];
    __shared__ float epart[128];
    __shared__ float redm[4], reds[4];
    hs[tid]       = g_h[par][b*MM + tid];
    hs[tid + 256] = g_c[par][b*MM + tid];
    if (tid < 64) ves[tid] = v_e[tid];
    __syncthreads();
    // hsW[t] = sum_k hs[k] * WU_e[t,k]; warp w handles t = w*8 .. w*8+7
    #pragma unroll
    for (int t = w*8; t < w*8 + 8; ++t) {
        const float* row = WU_e + t*576;
        float s = 0.f;
        #pragma unroll
        for (int k = l; k < 512; k += 32) s += hs[k] * row[k];
        s = wredsum(s);
        if (l == 0) hsW_s[t] = s;
    }
    __syncthreads();
    int half = tid >> 7, n = tid & 127;
    float e = 0.f;
    {
        const float* xp = g_Xp + b*TT*NN + half*32*NN + n;
        const float* vh = ves + half*32;
        const float* hh = hsW_s + half*32;
        #pragma unroll 8
        for (int t = 0; t < 32; ++t) e += vh[t] * fast_tanh(hh[t] + xp[t*NN]);
    }
    if (half == 1) epart[n] = e;
    __syncthreads();
    float p = 0.f;
    if (half == 0) {
        e += epart[n];
        float m = wredmax(e);
        if (l == 0) redm[w] = m;
    }
    __syncthreads();
    if (half == 0) {
        float m = fmaxf(fmaxf(redm[0], redm[1]), fmaxf(redm[2], redm[3]));
        p = __expf(e - m);
        float s = wredsum(p);
        if (l == 0) reds[w] = s;
    }
    __syncthreads();
    if (half == 0) {
        float tot = reds[0] + reds[1] + reds[2] + reds[3];
        float alpha = __fdividef(p, tot);
        g_xin[b*NN + n] = inp[b*TT*INROW + step*INROW + n] * alpha;
    }
}

// ---------------- encoder gates GEMM + fused LSTM ----------------
// grid (16,16): tile 16 batch x 64 gate-cols. 256 threads = 2 K-groups of 128.
// cp.async 2-stage pipeline; 2x4 micro-tile per thread.
__global__ void __launch_bounds__(256) k_enc_gates(
        const float* __restrict__ Wih, const float* __restrict__ Whh,
        const float* __restrict__ bih, const float* __restrict__ bhh,
        int step, int par) {
    int bb = blockIdx.x, mo = blockIdx.y;
    int tid = threadIdx.x;
    int kg = tid >> 7;            // 0 or 1
    int t128 = tid & 127;
    int ty = t128 >> 4, tx = t128 & 15;
    __shared__ float A_s[2][2][32][18];   // [stage][kg][kk][row]
    __shared__ float W_s[2][2][32][68];   // [stage][kg][kk][col]
    __shared__ float red[16][65];
    float acc[2][4];
    #pragma unroll
    for (int i = 0; i < 2; ++i)
        #pragma unroll
        for (int j = 0; j < 4; ++j) acc[i][j] = 0.f;
    const float* hsrc = g_h[par];
    int kbase = kg * 192;

    // issue cp.async loads for chunk c into stage st
    #define ENC_ISSUE(c, st) do {                                              \
        int kc = kbase + (c)*32;                                               \
        _Pragma("unroll")                                                      \
        for (int u = 0; u < 4; ++u) {                                          \
            int idx = t128 + u*128;                                            \
            int row = idx >> 5, kk = idx & 31;                                 \
            int k = kc + kk, gb = bb*16 + row;                                 \
            const float* src = (k < 128) ? (g_xin + gb*NN + k)                 \
                                         : (hsrc + gb*MM + (k - 128));         \
            cp4(&A_s[st][kg][kk][row], src);                                   \
        }                                                                      \
        _Pragma("unroll")                                                      \
        for (int u = 0; u < 16; ++u) {                                         \
            int idx = t128 + u*128;                                            \
            int co = idx >> 5, kk = idx & 31;                                  \
            int row = (co >> 4)*256 + mo*16 + (co & 15);                       \
            int k = kc + kk;                                                   \
            const float* src = (k < 128) ? (Wih + row*128 + k)                 \
                                         : (Whh + row*256 + (k - 128));        \
            cp4(&W_s[st][kg][kk][co], src);                                    \
        }                                                                      \
        cp_commit();                                                           \
    } while (0)

    ENC_ISSUE(0, 0);
    #pragma unroll
    for (int c = 0; c < 6; ++c) {
        int st = c & 1;
        if (c < 5) { ENC_ISSUE(c + 1, st ^ 1); cp_wait<1>(); }
        else       { cp_wait<0>(); }
        __syncthreads();
        #pragma unroll
        for (int kk = 0; kk < 32; ++kk) {
            float2 a = *(const float2*)&A_s[st][kg][kk][ty*2];
            float4 w = *(const float4*)&W_s[st][kg][kk][tx*4];
            acc[0][0] += a.x*w.x; acc[0][1] += a.x*w.y; acc[0][2] += a.x*w.z; acc[0][3] += a.x*w.w;
            acc[1][0] += a.y*w.x; acc[1][1] += a.y*w.y; acc[1][2] += a.y*w.z; acc[1][3] += a.y*w.w;
        }
        __syncthreads();
    }
    #undef ENC_ISSUE

    if (kg == 0) {
        #pragma unroll
        for (int i = 0; i < 2; ++i)
            #pragma unroll
            for (int j = 0; j < 4; ++j) red[ty*2 + i][tx*4 + j] = acc[i][j];
    }
    __syncthreads();
    if (kg == 1) {
        #pragma unroll
        for (int i = 0; i < 2; ++i)
            #pragma unroll
            for (int j = 0; j < 4; ++j) red[ty*2 + i][tx*4 + j] += acc[i][j];
    }
    __syncthreads();
    {
        int bi = tid >> 4, ml = tid & 15;
        int gb = bb*16 + bi, m = mo*16 + ml;
        float gi = red[bi][ml]      + bih[m]       + bhh[m];
        float gf = red[bi][16 + ml] + bih[256 + m] + bhh[256 + m];
        float gg = red[bi][32 + ml] + bih[512 + m] + bhh[512 + m];
        float go = red[bi][48 + ml] + bih[768 + m] + bhh[768 + m];
        float cold = g_c[par][gb*MM + m];
        float cn = fast_sigm(gf)*cold + fast_sigm(gi)*fast_tanh(gg);
        float hn = fast_sigm(go)*fast_tanh(cn);
        g_c[par ^ 1][gb*MM + m] = cn;
        g_h[par ^ 1][gb*MM + m] = hn;
        g_Xe[(gb*TT + step)*MM + m] = hn;
    }
}

// ---------------- precompute Xd[b][t][m] = sum_k Xe[b,t,k] * WU_d[m, 512+k] ----------------
__global__ void k_xd(const float* __restrict__ WU_d) {
    int rb = blockIdx.x, ob = blockIdx.y;
    int tid = threadIdx.x;
    int ty = tid >> 4, tx = tid & 15;
    __shared__ float A_s[32][68];
    __shared__ float W_s[32][68];
    float acc[4][4];
    #pragma unroll
    for (int i = 0; i < 4; ++i)
        #pragma unroll
        for (int j = 0; j < 4; ++j) acc[i][j] = 0.f;
    for (int kc = 0; kc < 256; kc += 32) {
        for (int idx = tid; idx < 2048; idx += 256) {
            int ri = idx >> 5, kk = idx & 31;
            A_s[kk][ri] = g_Xe[(rb*64 + ri)*MM + kc + kk];
        }
        for (int idx = tid; idx < 2048; idx += 256) {
            int co = idx >> 5, kk = idx & 31;
            W_s[kk][co] = WU_d[(ob*64 + co)*768 + 512 + kc + kk];
        }
        __syncthreads();
        #pragma unroll
        for (int kk = 0; kk < 32; ++kk) {
            float4 a = *(const float4*)&A_s[kk][ty*4];
            float4 w = *(const float4*)&W_s[kk][tx*4];
            acc[0][0] += a.x*w.x; acc[0][1] += a.x*w.y; acc[0][2] += a.x*w.z; acc[0][3] += a.x*w.w;
            acc[1][0] += a.y*w.x; acc[1][1] += a.y*w.y; acc[1][2] += a.y*w.z; acc[1][3] += a.y*w.w;
            acc[2][0] += a.z*w.x; acc[2][1] += a.z*w.y; acc[2][2] += a.z*w.z; acc[2][3] += a.z*w.w;
            acc[3][0] += a.w*w.x; acc[3][1] += a.w*w.y; acc[3][2] += a.w*w.z; acc[3][3] += a.w*w.w;
        }
        __syncthreads();
    }
    #pragma unroll
    for (int i = 0; i < 4; ++i)
        #pragma unroll
        for (int j = 0; j < 4; ++j)
            g_Xd[(rb*64 + ty*4 + i)*MM + ob*64 + tx*4 + j] = acc[i][j];
}

// ---------------- decoder hsW GEMM: (B,512)[h|c] @ WU_d[:, :512]^T -> (B,256) ----------------
__global__ void __launch_bounds__(256) k_dec_hsw(const float* __restrict__ WU_d, int par) {
    int rb = blockIdx.x, ob = blockIdx.y;
    int tid = threadIdx.x;
    int kg = tid >> 7;
    int t128 = tid & 127;
    int ty = t128 >> 4, tx = t128 & 15;
    __shared__ float A_s[2][32][20];
    __shared__ float W_s[2][32][20];
    __shared__ float red[16][17];
    float a0 = 0.f, a1 = 0.f;
    int kbase = kg * 256;
    for (int c = 0; c < 8; ++c) {
        int kc = kbase + c*32;
        #pragma unroll
        for (int u = 0; u < 4; ++u) {
            int idx = t128 + u*128;
            int ri = idx >> 5, kk = idx & 31;
            int k = kc + kk, gb = rb*16 + ri;
            A_s[kg][kk][ri] = (k < 256) ? g_h[par][gb*MM + k] : g_c[par][gb*MM + k - 256];
        }
        #pragma unroll
        for (int u = 0; u < 4; ++u) {
            int idx = t128 + u*128;
            int co = idx >> 5, kk = idx & 31;
            W_s[kg][kk][co] = WU_d[(ob*16 + co)*768 + kc + kk];
        }
        __syncthreads();
        #pragma unroll
        for (int kk = 0; kk < 32; ++kk) {
            float2 a = *(const float2*)&A_s[kg][kk][ty*2];
            float w = W_s[kg][kk][tx];
            a0 += a.x*w; a1 += a.y*w;
        }
        __syncthreads();
    }
    if (kg == 0) {
        red[ty*2][tx] = a0; red[ty*2 + 1][tx] = a1;
    }
    __syncthreads();
    if (kg == 1) {
        red[ty*2][tx] += a0; red[ty*2 + 1][tx] += a1;
    }
    __syncthreads();
    {
        int ri = tid >> 4, co = tid & 15;
        g_hsW[(rb*16 + ri)*MM + ob*16 + co] = red[ri][co];
    }
}

// ---------------- decoder attention: l, beta, ctx, y_tilde ----------------
__global__ void k_dec_att(const float* __restrict__ inp, const float* __restrict__ v_d,
                          const float* __restrict__ wbt, int step, int par) {
    int b = blockIdx.x;
    int tid = threadIdx.x;   // 256
    int w = tid >> 5, l = tid & 31;
    __shared__ float hsw_s[256], vds[256], l_s[64], beta_s[64], reds[8];
    hsw_s[tid] = g_hsW[b*MM + tid];
    vds[tid] = v_d[tid];
    __syncthreads();
    for (int t = w; t < 64; t += 8) {
        const float* xd = g_Xd + (b*TT + t)*MM;
        float s = 0.f;
        #pragma unroll
        for (int m = l; m < 256; m += 32) s += vds[m] * fast_tanh(hsw_s[m] + xd[m]);
        s = wredsum(s);
        if (l == 0) l_s[t] = s;
    }
    __syncthreads();
    if (tid < 32) {
        float a0 = l_s[tid], a1 = l_s[tid + 32];
        float mx = wredmax(fmaxf(a0, a1));
        mx = __shfl_sync(0xffffffffu, mx, 0);
        float p0 = __expf(a0 - mx), p1 = __expf(a1 - mx);
        float sm = wredsum(p0 + p1);
        sm = __shfl_sync(0xffffffffu, sm, 0);
        beta_s[tid] = __fdividef(p0, sm);
        beta_s[tid + 32] = __fdividef(p1, sm);
    }
    __syncthreads();
    float c = 0.f;
    const float* xe = g_Xe + b*TT*MM + tid;
    #pragma unroll 8
    for (int t = 0; t < 64; ++t) c += beta_s[t] * xe[t*MM];
    g_ctx[b*MM + tid] = c;
    float part = wbt[1 + tid] * c;
    part = wredsum(part);
    if (l == 0) reds[w] = part;
    __syncthreads();
    if (tid == 0) {
        float tot = 0.f;
        #pragma unroll
        for (int i = 0; i < 8; ++i) tot += reds[i];
        g_yt[b] = wbt[0] * inp[b*TT*INROW + step*INROW + 128] + tot;
    }
}

// ---------------- decoder gates GEMM (K=256) + fused LSTM, cp.async pipeline ----------------
__global__ void __launch_bounds__(256) k_dec_gates(
        const float* __restrict__ Wihd, const float* __restrict__ Whh,
        const float* __restrict__ bih, const float* __restrict__ bhh,
        int par) {
    int bb = blockIdx.x, mo = blockIdx.y;
    int tid = threadIdx.x;
    int kg = tid >> 7;
    int t128 = tid & 127;
    int ty = t128 >> 4, tx = t128 & 15;
    __shared__ float A_s[2][2][32][18];
    __shared__ float W_s[2][2][32][68];
    __shared__ float red[16][65];
    float acc[2][4];
    #pragma unroll
    for (int i = 0; i < 2; ++i)
        #pragma unroll
        for (int j = 0; j < 4; ++j) acc[i][j] = 0.f;
    const float* hsrc = g_h[par];
    int kbase = kg * 128;

    #define DEC_ISSUE(c, st) do {                                              \
        int kc = kbase + (c)*32;                                               \
        _Pragma("unroll")                                                      \
        for (int u = 0; u < 4; ++u) {                                          \
            int idx = t128 + u*128;                                            \
            int row = idx >> 5, kk = idx & 31;                                 \
            cp4(&A_s[st][kg][kk][row], hsrc + (bb*16 + row)*MM + kc + kk);     \
        }                                                                      \
        _Pragma("unroll")                                                      \
        for (int u = 0; u < 16; ++u) {                                         \
            int idx = t128 + u*128;                                            \
            int co = idx >> 5, kk = idx & 31;                                  \
            int row = (co >> 4)*256 + mo*16 + (co & 15);                       \
            cp4(&W_s[st][kg][kk][co], Whh + row*256 + kc + kk);                \
        }                                                                      \
        cp_commit();                                                           \
    } while (0)

    DEC_ISSUE(0, 0);
    #pragma unroll
    for (int c = 0; c < 4; ++c) {
        int st = c & 1;
        if (c < 3) { DEC_ISSUE(c + 1, st ^ 1); cp_wait<1>(); }
        else       { cp_wait<0>(); }
        __syncthreads();
        #pragma unroll
        for (int kk = 0; kk < 32; ++kk) {
            float2 a = *(const float2*)&A_s[st][kg][kk][ty*2];
            float4 w = *(const float4*)&W_s[st][kg][kk][tx*4];
            acc[0][0] += a.x*w.x; acc[0][1] += a.x*w.y; acc[0][2] += a.x*w.z; acc[0][3] += a.x*w.w;
            acc[1][0] += a.y*w.x; acc[1][1] += a.y*w.y; acc[1][2] += a.y*w.z; acc[1][3] += a.y*w.w;
        }
        __syncthreads();
    }
    #undef DEC_ISSUE

    if (kg == 0) {
        #pragma unroll
        for (int i = 0; i < 2; ++i)
            #pragma unroll
            for (int j = 0; j < 4; ++j) red[ty*2 + i][tx*4 + j] = acc[i][j];
    }
    __syncthreads();
    if (kg == 1) {
        #pragma unroll
        for (int i = 0; i < 2; ++i)
            #pragma unroll
            for (int j = 0; j < 4; ++j) red[ty*2 + i][tx*4 + j] += acc[i][j];
    }
    __syncthreads();
    {
        int bi = tid >> 4, ml = tid & 15;
        int gb = bb*16 + bi, m = mo*16 + ml;
        float yt = g_yt[gb];
        float gi = red[bi][ml]      + bih[m]       + bhh[m]       + yt*Wihd[m];
        float gf = red[bi][16 + ml] + bih[256 + m] + bhh[256 + m] + yt*Wihd[256 + m];
        float gg = red[bi][32 + ml] + bih[512 + m] + bhh[512 + m] + yt*Wihd[512 + m];
        float go = red[bi][48 + ml] + bih[768 + m] + bhh[768 + m] + yt*Wihd[768 + m];
        float cold = g_c[par][gb*MM + m];
        float cn = fast_sigm(gf)*cold + fast_sigm(gi)*fast_tanh(gg);
        float hn = fast_sigm(go)*fast_tanh(cn);
        g_c[par ^ 1][gb*MM + m] = cn;
        g_h[par ^ 1][gb*MM + m] = hn;
    }
}

// ---------------- final projection ----------------
__global__ void k_final(const float* __restrict__ WbW, const float* __restrict__ Wbb,
                        const float* __restrict__ vbW, const float* __restrict__ vbb,
                        float* __restrict__ out, int par) {
    int b = blockIdx.x;
    int tid = threadIdx.x;   // 256
    int w = tid >> 5, l = tid & 31;
    __shared__ float hc[512];
    __shared__ float hid[256];
    __shared__ float reds[8];
    hc[tid]       = g_h[par][b*MM + tid];
    hc[256 + tid] = g_ctx[b*MM + tid];
    __syncthreads();
    for (int p = w*32; p < w*32 + 32; ++p) {
        const float* row = WbW + p*512;
        float s = 0.f;
        #pragma unroll
        for (int k = l; k < 512; k += 32) s += hc[k] * row[k];
        s = wredsum(s);
        if (l == 0) hid[p] = s + Wbb[p];
    }
    __syncthreads();
    float part = hid[tid] * vbW[tid];
    part = wredsum(part);
    if (l == 0) reds[w] = part;
    __syncthreads();
    if (tid == 0) {
        float tot = 0.f;
        #pragma unroll
        for (int i = 0; i < 8; ++i) tot += reds[i];
        out[b] = tot + vbb[0];
    }
}

// ---------------- launcher ----------------
extern "C" void kernel_launch(void* const* d_in, const int* in_sizes, int n_in,
                              void* d_out, int out_size) {
    const float* inp   = (const float*)d_in[0];
    const float* WU_e  = (const float*)d_in[1];
    const float* v_e   = (const float*)d_in[2];
    const float* Wih_e = (const float*)d_in[3];
    const float* Whh_e = (const float*)d_in[4];
    const float* bih_e = (const float*)d_in[5];
    const float* bhh_e = (const float*)d_in[6];
    const float* WU_d  = (const float*)d_in[7];
    const float* v_d   = (const float*)d_in[8];
    const float* wbt   = (const float*)d_in[9];
    const float* Wih_d = (const float*)d_in[10];
    const float* Whh_d = (const float*)d_in[11];
    const float* bih_d = (const float*)d_in[12];
    const float* bhh_d = (const float*)d_in[13];
    const float* WbW   = (const float*)d_in[14];
    const float* Wbb   = (const float*)d_in[15];
    const float* vbW   = (const float*)d_in[16];
    const float* vbb   = (const float*)d_in[17];
    float* out = (float*)d_out;

    k_init<<<256, 256>>>();
    k_xp<<<256, 128>>>(inp, WU_e);

    for (int s = 0; s < 64; ++s) {
        int par = s & 1;
        k_enc_att<<<256, 256>>>(inp, WU_e, v_e, s, par);
        k_enc_gates<<<dim3(16, 16), 256>>>(Wih_e, Whh_e, bih_e, bhh_e, s, par);
    }

    k_xd<<<dim3(256, 4), 256>>>(WU_d);
    k_init<<<256, 256>>>();

    for (int s = 0; s < 63; ++s) {
        int par = s & 1;
        k_dec_hsw<<<dim3(16, 16), 256>>>(WU_d, par);
        k_dec_att<<<256, 256>>>(inp, v_d, wbt, s, par);
        k_dec_gates<<<dim3(16, 16), 256>>>(Wih_d, Whh_d, bih_d, bhh_d, par);
    }

    // after 63 decoder steps, final h/c live in parity (63 & 1) = 1
    k_final<<<256, 256>>>(WbW, Wbb, vbW, vbb, out, 1);
}